// round 1
// baseline (speedup 1.0000x reference)
#include <cuda_runtime.h>
#include <math.h>

// Problem constants
#define HH      256
#define NPOLES  32
#define LLEN    8192
#define LH      4097      // L/2 + 1
#define MHALF   4096      // L/2

// Scratch: half-spectrum k_f per (h, l), complex fp32. 256*4097*8B = 8.39 MB.
__device__ float2 g_kf[HH * LH];

// ---------------------------------------------------------------------------
// Kernel 1: Cauchy kernel + rank-1 Woodbury + bilinear scale -> g_kf[h][l]
//
// z_l = 2i * tan(pi*l/L)   (exactly imaginary: Re(z)=0)
// r_sc(l) = dt * sum_n [ v_sc/(z - w) + conj(v_sc)/(z - conj(w)) ]
// k_f = (r00 - r01*r10/(1+r11)) * (1 + i*tan(pi*l/L))
// ---------------------------------------------------------------------------
__global__ __launch_bounds__(128) void cauchy_kernel(
    const float* __restrict__ w_re, const float* __restrict__ w_im,
    const float* __restrict__ p_re, const float* __restrict__ p_im,
    const float* __restrict__ B_re, const float* __restrict__ B_im,
    const float* __restrict__ C_re, const float* __restrict__ C_im,
    const float* __restrict__ log_dt)
{
    __shared__ float snwr[NPOLES], swi[NPOLES], swr2[NPOLES];
    __shared__ float v00r[NPOLES], v00i[NPOLES];
    __shared__ float v01r[NPOLES], v01i[NPOLES];
    __shared__ float v10r[NPOLES], v10i[NPOLES];
    __shared__ float v11s[NPOLES];

    const int h   = blockIdx.y;
    const int tid = threadIdx.x;

    if (tid < NPOLES) {
        const int n   = tid;
        const int idx = h * NPOLES + n;
        const float dt = expf(log_dt[h]);
        const float wr = w_re[idx] * dt;
        const float wi = w_im[idx] * dt;
        const float Br = B_re[idx], Bi = B_im[idx];
        const float Cr = C_re[idx], Ci = C_im[idx];
        const float Pr = p_re[idx], Pi = p_im[idx];
        snwr[n] = -wr;
        swi[n]  = wi;
        swr2[n] = wr * wr;
        // v_sc = Bs[s]*Cs[c], dt folded in. Bs = {B, P}, Cs = {C, conj(P)}
        v00r[n] = (Br * Cr - Bi * Ci) * dt;   // B*C
        v00i[n] = (Br * Ci + Bi * Cr) * dt;
        v01r[n] = (Br * Pr + Bi * Pi) * dt;   // B*conj(P)
        v01i[n] = (Bi * Pr - Br * Pi) * dt;
        v10r[n] = (Pr * Cr - Pi * Ci) * dt;   // P*C
        v10i[n] = (Pr * Ci + Pi * Cr) * dt;
        v11s[n] = (Pr * Pr + Pi * Pi) * dt;   // P*conj(P) (real)
    }
    __syncthreads();

    const int l = blockIdx.x * blockDim.x + tid;
    if (l >= LH) return;

    if (l == MHALF) {
        // Nyquist: analytic limit z -> inf:  k_f = sum_n Re(v00) (dt folded)
        float acc = 0.0f;
        #pragma unroll
        for (int n = 0; n < NPOLES; n++) acc += v00r[n];
        g_kf[h * LH + l] = make_float2(acc, 0.0f);
        return;
    }

    float sp, cp;
    sincospif((float)l / (float)LLEN, &sp, &cp);
    const float t  = sp / cp;          // tan(pi*l/L), l < L/2 so cp > 0
    const float zy = 2.0f * t;         // z = i*zy

    float r00re = 0.f, r00im = 0.f, r01re = 0.f, r01im = 0.f;
    float r10re = 0.f, r10im = 0.f, r11re = 0.f, r11im = 0.f;

    #pragma unroll 8
    for (int n = 0; n < NPOLES; n++) {
        const float wi  = swi[n];
        const float nwr = snwr[n];
        const float wr2 = swr2[n];
        const float dy1 = zy - wi;
        const float dy2 = zy + wi;
        const float m1  = fmaf(dy1, dy1, wr2);
        const float m2  = fmaf(dy2, dy2, wr2);
        const float inv = __frcp_rn(m1 * m2);    // single MUFU for both recips
        const float s1  = m2 * inv;
        const float s2  = m1 * inv;
        // cw  = 1/(z-w)      = (nwr - i*dy1) * s1
        // cwc = 1/(z-conj w) = (nwr - i*dy2) * s2
        const float cx1 = nwr * s1, cy1 = -dy1 * s1;
        const float cx2 = nwr * s2, cy2 = -dy2 * s2;
        const float A  = cx1 + cx2;
        const float Bm = cx1 - cx2;
        const float Cp = cy1 + cy2;
        const float Dm = cy2 - cy1;
        // r += v*cw + conj(v)*cwc : re += vr*A + vi*Dm ; im += vr*Cp + vi*Bm
        r00re = fmaf(v00r[n], A,  fmaf(v00i[n], Dm, r00re));
        r00im = fmaf(v00r[n], Cp, fmaf(v00i[n], Bm, r00im));
        r01re = fmaf(v01r[n], A,  fmaf(v01i[n], Dm, r01re));
        r01im = fmaf(v01r[n], Cp, fmaf(v01i[n], Bm, r01im));
        r10re = fmaf(v10r[n], A,  fmaf(v10i[n], Dm, r10re));
        r10im = fmaf(v10r[n], Cp, fmaf(v10i[n], Bm, r10im));
        r11re = fmaf(v11s[n], A,  r11re);
        r11im = fmaf(v11s[n], Cp, r11im);
    }

    // Woodbury: kw = r00 - r01*r10/(1+r11)
    const float dre  = 1.0f + r11re;
    const float dim  = r11im;
    const float dinv = __frcp_rn(fmaf(dre, dre, dim * dim));
    const float numre = r01re * r10re - r01im * r10im;
    const float numim = r01re * r10im + r01im * r10re;
    const float qre = (numre * dre + numim * dim) * dinv;
    const float qim = (numim * dre - numre * dim) * dinv;
    const float kwre = r00re - qre;
    const float kwim = r00im - qim;
    // * 2/(1+omega) = (1 + i*t)
    const float kfre = kwre - kwim * t;
    const float kfim = fmaf(kwre, t, kwim);
    g_kf[h * LH + l] = make_float2(kfre, kfim);
}

// ---------------------------------------------------------------------------
// Kernel 2: per-h irfft(L=8192) via M=4096 complex inverse FFT.
// Unpack: E[k] = (K[k]+conj(K[M-k]))/2, O[k] = (K[k]-conj(K[M-k]))/2 * e^{+2pi i k/L}
//         Y[k] = E[k] + i*O[k];  y = (1/M) * IDFT_M(Y);  x[2m]=Re y, x[2m+1]=Im y
// IDFT: radix-2 Stockham, ping-pong in shared (naturally ordered output).
// ---------------------------------------------------------------------------
__global__ __launch_bounds__(512) void ifft_kernel(float* __restrict__ out)
{
    extern __shared__ float2 sh[];      // 2 * 4096 * float2 = 64 KB
    float2* bufA = sh;
    float2* bufB = sh + MHALF;

    const int h   = blockIdx.x;
    const int tid = threadIdx.x;
    const float scale = 1.0f / (float)MHALF;
    const float2* __restrict__ K = &g_kf[h * LH];

    // Build Y (scale folded in)
    for (int k = tid; k < MHALF; k += 512) {
        float2 Kk = K[k];
        float2 Km = K[MHALF - k];
        if (k == 0) { Kk.y = 0.0f; Km.y = 0.0f; }  // irfft ignores imag of DC/Nyquist
        const float Ere = 0.5f * (Kk.x + Km.x);
        const float Eim = 0.5f * (Kk.y - Km.y);
        const float Dre = 0.5f * (Kk.x - Km.x);
        const float Dim = 0.5f * (Kk.y + Km.y);
        float tws, twc;
        sincospif((float)k / (float)MHALF, &tws, &twc);  // e^{+2pi i k / L}
        const float Ore = Dre * twc - Dim * tws;
        const float Oim = Dre * tws + Dim * twc;
        bufA[k] = make_float2((Ere - Oim) * scale, (Eim + Ore) * scale);
    }
    __syncthreads();

    // 12 radix-2 Stockham stages (inverse: e^{+2pi i p/ncur} twiddles)
    float2* src = bufA;
    float2* dst = bufB;
    int s  = 1;
    int ls = 0;
    for (int ncur = MHALF; ncur > 1; ncur >>= 1, s <<= 1, ls++) {
        const int m = ncur >> 1;
        const float invn = 2.0f / (float)ncur;     // 2*p/ncur for sincospif
        for (int bi = tid; bi < (MHALF >> 1); bi += 512) {
            const int q = bi & (s - 1);
            const int p = bi >> ls;
            float tws, twc;
            sincospif((float)p * invn, &tws, &twc);
            const float2 u = src[q + s * p];
            const float2 v = src[q + s * (p + m)];
            const float2 sum = make_float2(u.x + v.x, u.y + v.y);
            const float2 dif = make_float2(u.x - v.x, u.y - v.y);
            dst[q + s * (2 * p)]     = sum;
            dst[q + s * (2 * p + 1)] = make_float2(dif.x * twc - dif.y * tws,
                                                   dif.x * tws + dif.y * twc);
        }
        __syncthreads();
        float2* tmp = src; src = dst; dst = tmp;
    }

    // src == bufA after 12 stages; interleave (Re,Im) = (x[2m], x[2m+1])
    float2* o2 = reinterpret_cast<float2*>(out) + h * MHALF;
    for (int m2 = tid; m2 < MHALF; m2 += 512) {
        o2[m2] = src[m2];
    }
}

// ---------------------------------------------------------------------------
extern "C" void kernel_launch(void* const* d_in, const int* in_sizes, int n_in,
                              void* d_out, int out_size)
{
    const float* w_re   = (const float*)d_in[0];
    const float* w_im   = (const float*)d_in[1];
    const float* p_re   = (const float*)d_in[2];
    const float* p_im   = (const float*)d_in[3];
    const float* B_re   = (const float*)d_in[4];
    const float* B_im   = (const float*)d_in[5];
    const float* C_re   = (const float*)d_in[6];
    const float* C_im   = (const float*)d_in[7];
    const float* log_dt = (const float*)d_in[8];
    float* out = (float*)d_out;

    (void)in_sizes; (void)n_in; (void)out_size;

    // Opt-in to 64 KB dynamic shared for the FFT kernel (idempotent, not a
    // stream op, safe under graph capture).
    cudaFuncSetAttribute(ifft_kernel,
                         cudaFuncAttributeMaxDynamicSharedMemorySize, 65536);

    dim3 grid1((LH + 127) / 128, HH);
    cauchy_kernel<<<grid1, 128>>>(w_re, w_im, p_re, p_im,
                                  B_re, B_im, C_re, C_im, log_dt);

    ifft_kernel<<<HH, 512, 65536>>>(out);
}

// round 2
// speedup vs baseline: 1.3066x; 1.3066x over previous
#include <cuda_runtime.h>
#include <math.h>

// Problem constants
#define HH      256
#define NPOLES  32
#define LLEN    8192
#define LH      4097
#define MHALF   4096
#define KSTRIDE 4104       // padded row stride (16B-aligned rows for float4 stores)

// Scratch: half-spectrum k_f per (h, l). 256*4104*8B = 8.4 MB.
__device__ float2 g_kf[HH * KSTRIDE];

typedef unsigned long long u64;

// ---- packed f32x2 helpers (Blackwell sm_100a) -----------------------------
__device__ __forceinline__ u64 f2add(u64 a, u64 b) {
    u64 d; asm("add.rn.f32x2 %0,%1,%2;" : "=l"(d) : "l"(a), "l"(b)); return d;
}
__device__ __forceinline__ u64 f2mul(u64 a, u64 b) {
    u64 d; asm("mul.rn.f32x2 %0,%1,%2;" : "=l"(d) : "l"(a), "l"(b)); return d;
}
__device__ __forceinline__ u64 f2fma(u64 a, u64 b, u64 c) {
    u64 d; asm("fma.rn.f32x2 %0,%1,%2,%3;" : "=l"(d) : "l"(a), "l"(b), "l"(c)); return d;
}
__device__ __forceinline__ u64 f2rcp(u64 a) {
    u64 d;
    asm("{\n\t.reg .f32 lo,hi,rl,rh;\n\t"
        "mov.b64 {lo,hi}, %1;\n\t"
        "rcp.approx.f32 rl, lo;\n\t"
        "rcp.approx.f32 rh, hi;\n\t"
        "mov.b64 %0, {rl,rh};\n\t}" : "=l"(d) : "l"(a));
    return d;
}
__device__ __forceinline__ u64 pack2(float x, float y) {
    u64 d; asm("mov.b64 %0, {%1,%2};" : "=l"(d) : "f"(x), "f"(y)); return d;
}
__device__ __forceinline__ void unpack2(u64 a, float& x, float& y) {
    asm("mov.b64 {%0,%1}, %2;" : "=f"(x), "=f"(y) : "l"(a));
}

// constant slot indices
#define C_AW   0
#define C_NAW  1
#define C_NB   2
#define C_FWR2 3
#define C_NWR  4
#define C_KB2  5
#define C_WI   6
#define C_V00R 7
#define C_V00I 8
#define C_V01R 9
#define C_V01I 10
#define C_V10R 11
#define C_V10I 12
#define C_V11  13

// per-lane Woodbury epilogue (im accumulators arrive negated)
__device__ __forceinline__ float2 woodbury(
    float r00r, float n00, float r01r, float n01,
    float r10r, float n10, float r11r, float n11, float t)
{
    const float r00i = -n00, r01i = -n01, r10i = -n10, r11i = -n11;
    const float dre  = 1.0f + r11r;
    const float dim  = r11i;
    const float dinv = __frcp_rn(fmaf(dre, dre, dim * dim));
    const float numre = r01r * r10r - r01i * r10i;
    const float numim = r01r * r10i + r01i * r10r;
    const float qre = (numre * dre + numim * dim) * dinv;
    const float qim = (numim * dre - numre * dim) * dinv;
    const float kwre = r00r - qre;
    const float kwim = r00i - qim;
    return make_float2(kwre - kwim * t, fmaf(kwre, t, kwim));
}

// ---------------------------------------------------------------------------
// Kernel 1: Cauchy + rank-1 Woodbury + bilinear scale -> g_kf[h][l]
// z = 2i*tan(pi*l/L) purely imaginary. Per thread: 4 l's as 2 f32x2 pairs.
// ---------------------------------------------------------------------------
__global__ __launch_bounds__(128) void cauchy_kernel(
    const float* __restrict__ w_re, const float* __restrict__ w_im,
    const float* __restrict__ p_re, const float* __restrict__ p_im,
    const float* __restrict__ B_re, const float* __restrict__ B_im,
    const float* __restrict__ C_re, const float* __restrict__ C_im,
    const float* __restrict__ log_dt)
{
    __shared__ float2 cst[NPOLES][16];   // duplicated-value packed constants

    const int h   = blockIdx.y;
    const int tid = threadIdx.x;

    if (tid < NPOLES) {
        const int n   = tid;
        const int idx = h * NPOLES + n;
        const float dt = expf(log_dt[h]);
        const float wr = w_re[idx] * dt;
        const float wi = w_im[idx] * dt;
        const float Br = B_re[idx], Bi = B_im[idx];
        const float Cr = C_re[idx], Ci = C_im[idx];
        const float Pr = p_re[idx], Pi = p_im[idx];
        const float aw = wr * wr + wi * wi;
        const float b  = wi * wi - wr * wr;
        const float d2 = 2.0f * dt;
        float2* cn = cst[n];
        cn[C_AW]   = make_float2(aw, aw);
        cn[C_NAW]  = make_float2(-aw, -aw);
        cn[C_NB]   = make_float2(-b, -b);
        cn[C_FWR2] = make_float2(4.0f * wr * wr, 4.0f * wr * wr);
        cn[C_NWR]  = make_float2(-wr, -wr);
        cn[C_KB2]  = make_float2(2.0f * wr * wi, 2.0f * wr * wi);
        cn[C_WI]   = make_float2(wi, wi);
        float v;
        v = d2 * (Br * Cr - Bi * Ci); cn[C_V00R] = make_float2(v, v);
        v = d2 * (Br * Ci + Bi * Cr); cn[C_V00I] = make_float2(v, v);
        v = d2 * (Br * Pr + Bi * Pi); cn[C_V01R] = make_float2(v, v);
        v = d2 * (Bi * Pr - Br * Pi); cn[C_V01I] = make_float2(v, v);
        v = d2 * (Pr * Cr - Pi * Ci); cn[C_V10R] = make_float2(v, v);
        v = d2 * (Pr * Ci + Pi * Cr); cn[C_V10I] = make_float2(v, v);
        v = d2 * (Pr * Pr + Pi * Pi); cn[C_V11]  = make_float2(v, v);
    }
    __syncthreads();

    // Nyquist bin (z -> inf limit): k_f = sum_n Re(B*C)*dt
    if (blockIdx.x == 0 && tid == 0) {
        float acc = 0.0f;
        #pragma unroll
        for (int n = 0; n < NPOLES; n++) acc += 0.5f * cst[n][C_V00R].x;
        g_kf[h * KSTRIDE + MHALF] = make_float2(acc, 0.0f);
    }

    const int l0 = (blockIdx.x * 128 + tid) * 4;   // covers [0, 4096) exactly

    float t0, t1, t2, t3;
    {
        float s, c;
        sincospif((float)(l0 + 0) * (1.0f / LLEN), &s, &c); t0 = __fdividef(s, c);
        sincospif((float)(l0 + 1) * (1.0f / LLEN), &s, &c); t1 = __fdividef(s, c);
        sincospif((float)(l0 + 2) * (1.0f / LLEN), &s, &c); t2 = __fdividef(s, c);
        sincospif((float)(l0 + 3) * (1.0f / LLEN), &s, &c); t3 = __fdividef(s, c);
    }
    const u64 za = pack2(2.0f * t0, 2.0f * t1);
    const u64 zb = pack2(2.0f * t2, 2.0f * t3);
    const u64 ua = f2mul(za, za);
    const u64 ub = f2mul(zb, zb);

    u64 a00r = 0, a00n = 0, a01r = 0, a01n = 0, a10r = 0, a10n = 0, a11r = 0, a11n = 0;
    u64 b00r = 0, b00n = 0, b01r = 0, b01n = 0, b10r = 0, b10n = 0, b11r = 0, b11n = 0;

    #pragma unroll 2
    for (int n = 0; n < NPOLES; n++) {
        const u64* cn = reinterpret_cast<const u64*>(cst[n]);
        const u64 AW   = cn[C_AW];
        const u64 NAW  = cn[C_NAW];
        const u64 NB   = cn[C_NB];
        const u64 FWR2 = cn[C_FWR2];
        const u64 NWR  = cn[C_NWR];
        const u64 KB2  = cn[C_KB2];
        const u64 WI   = cn[C_WI];
        const u64 V00R = cn[C_V00R];
        const u64 V00I = cn[C_V00I];
        const u64 V01R = cn[C_V01R];
        const u64 V01I = cn[C_V01I];
        const u64 V10R = cn[C_V10R];
        const u64 V10I = cn[C_V10I];
        const u64 V11  = cn[C_V11];

        // ---- pair a ----
        {
            const u64 c1 = f2add(ua, AW);
            const u64 c2 = f2add(ua, NAW);
            const u64 c3 = f2add(ua, NB);
            const u64 m  = f2fma(c2, c2, f2mul(ua, FWR2));
            const u64 iv = f2rcp(m);
            const u64 ti = f2mul(za, iv);
            const u64 Ap = f2mul(f2mul(c1, iv), NWR);
            const u64 Bm = f2mul(KB2, ti);
            const u64 Cp = f2mul(c3, ti);
            const u64 Dm = f2mul(f2mul(c2, iv), WI);
            a00r = f2fma(V00R, Ap, f2fma(V00I, Dm, a00r));
            a00n = f2fma(V00R, Cp, f2fma(V00I, Bm, a00n));
            a01r = f2fma(V01R, Ap, f2fma(V01I, Dm, a01r));
            a01n = f2fma(V01R, Cp, f2fma(V01I, Bm, a01n));
            a10r = f2fma(V10R, Ap, f2fma(V10I, Dm, a10r));
            a10n = f2fma(V10R, Cp, f2fma(V10I, Bm, a10n));
            a11r = f2fma(V11, Ap, a11r);
            a11n = f2fma(V11, Cp, a11n);
        }
        // ---- pair b ----
        {
            const u64 c1 = f2add(ub, AW);
            const u64 c2 = f2add(ub, NAW);
            const u64 c3 = f2add(ub, NB);
            const u64 m  = f2fma(c2, c2, f2mul(ub, FWR2));
            const u64 iv = f2rcp(m);
            const u64 ti = f2mul(zb, iv);
            const u64 Ap = f2mul(f2mul(c1, iv), NWR);
            const u64 Bm = f2mul(KB2, ti);
            const u64 Cp = f2mul(c3, ti);
            const u64 Dm = f2mul(f2mul(c2, iv), WI);
            b00r = f2fma(V00R, Ap, f2fma(V00I, Dm, b00r));
            b00n = f2fma(V00R, Cp, f2fma(V00I, Bm, b00n));
            b01r = f2fma(V01R, Ap, f2fma(V01I, Dm, b01r));
            b01n = f2fma(V01R, Cp, f2fma(V01I, Bm, b01n));
            b10r = f2fma(V10R, Ap, f2fma(V10I, Dm, b10r));
            b10n = f2fma(V10R, Cp, f2fma(V10I, Bm, b10n));
            b11r = f2fma(V11, Ap, b11r);
            b11n = f2fma(V11, Cp, b11n);
        }
    }

    // epilogue: unpack, Woodbury per lane, packed stores
    float x0, x1;
    float r00r[4], n00[4], r01r[4], n01[4], r10r[4], n10[4], r11r[4], n11[4];
    unpack2(a00r, r00r[0], r00r[1]); unpack2(b00r, r00r[2], r00r[3]);
    unpack2(a00n, n00[0],  n00[1]);  unpack2(b00n, n00[2],  n00[3]);
    unpack2(a01r, r01r[0], r01r[1]); unpack2(b01r, r01r[2], r01r[3]);
    unpack2(a01n, n01[0],  n01[1]);  unpack2(b01n, n01[2],  n01[3]);
    unpack2(a10r, r10r[0], r10r[1]); unpack2(b10r, r10r[2], r10r[3]);
    unpack2(a10n, n10[0],  n10[1]);  unpack2(b10n, n10[2],  n10[3]);
    unpack2(a11r, r11r[0], r11r[1]); unpack2(b11r, r11r[2], r11r[3]);
    unpack2(a11n, n11[0],  n11[1]);  unpack2(b11n, n11[2],  n11[3]);
    (void)x0; (void)x1;

    const float2 kf0 = woodbury(r00r[0], n00[0], r01r[0], n01[0], r10r[0], n10[0], r11r[0], n11[0], t0);
    const float2 kf1 = woodbury(r00r[1], n00[1], r01r[1], n01[1], r10r[1], n10[1], r11r[1], n11[1], t1);
    const float2 kf2 = woodbury(r00r[2], n00[2], r01r[2], n01[2], r10r[2], n10[2], r11r[2], n11[2], t2);
    const float2 kf3 = woodbury(r00r[3], n00[3], r01r[3], n01[3], r10r[3], n10[3], r11r[3], n11[3], t3);

    float2* row = g_kf + h * KSTRIDE;
    reinterpret_cast<float4*>(row + l0)[0]     = make_float4(kf0.x, kf0.y, kf1.x, kf1.y);
    reinterpret_cast<float4*>(row + l0 + 2)[0] = make_float4(kf2.x, kf2.y, kf3.x, kf3.y);
}

// ---------------------------------------------------------------------------
// Kernel 2: per-h irfft(L=8192) via M=4096 complex inverse Stockham FFT.
// Shared twiddle table tw[k] = e^{+i*pi*k/4096}, serves both the C2R unpack
// twiddle (index k) and every stage twiddle (index p << (13-lg)).
// ---------------------------------------------------------------------------
__global__ __launch_bounds__(512) void ifft_kernel(float* __restrict__ out)
{
    extern __shared__ float2 sh[];          // bufA | bufB | tw : 96 KB
    float2* bufA = sh;
    float2* bufB = sh + MHALF;
    float2* tw   = sh + 2 * MHALF;

    const int h   = blockIdx.x;
    const int tid = threadIdx.x;

    for (int k = tid; k < MHALF; k += 512) {
        float s, c;
        sincospif((float)k * (1.0f / MHALF), &s, &c);
        tw[k] = make_float2(c, s);
    }
    __syncthreads();

    const float scale = 1.0f / (float)MHALF;
    const float2* __restrict__ K = &g_kf[h * KSTRIDE];

    for (int k = tid; k < MHALF; k += 512) {
        float2 Kk = K[k];
        float2 Km = K[MHALF - k];
        if (k == 0) { Kk.y = 0.0f; Km.y = 0.0f; }
        const float Ere = 0.5f * (Kk.x + Km.x);
        const float Eim = 0.5f * (Kk.y - Km.y);
        const float Dre = 0.5f * (Kk.x - Km.x);
        const float Dim = 0.5f * (Kk.y + Km.y);
        const float2 w = tw[k];
        const float Ore = Dre * w.x - Dim * w.y;
        const float Oim = Dre * w.y + Dim * w.x;
        bufA[k] = make_float2((Ere - Oim) * scale, (Eim + Ore) * scale);
    }
    __syncthreads();

    float2* src = bufA;
    float2* dst = bufB;
    const u64 NEG1 = pack2(-1.0f, -1.0f);
    int s = 1, ls = 0;
    for (int lg = 12; lg >= 1; lg--) {       // ncur = 1<<lg
        const int m   = 1 << (lg - 1);
        const int tsh = 13 - lg;
        for (int bi = tid; bi < (MHALF >> 1); bi += 512) {
            const int q = bi & (s - 1);
            const int p = bi >> ls;
            const u64 uu = *reinterpret_cast<const u64*>(&src[q + s * p]);
            const u64 vv = *reinterpret_cast<const u64*>(&src[q + s * (p + m)]);
            const u64 sum = f2add(uu, vv);
            const u64 dif = f2fma(vv, NEG1, uu);
            const float2 w = tw[p << tsh];
            float dx, dy; unpack2(dif, dx, dy);
            *reinterpret_cast<u64*>(&dst[q + s * 2 * p]) = sum;
            dst[q + s * (2 * p + 1)] = make_float2(dx * w.x - dy * w.y,
                                                   dx * w.y + dy * w.x);
        }
        __syncthreads();
        float2* tmp = src; src = dst; dst = tmp;
        s <<= 1; ls++;
    }

    float2* o2 = reinterpret_cast<float2*>(out) + (size_t)h * MHALF;
    for (int m2 = tid; m2 < MHALF; m2 += 512) {
        o2[m2] = src[m2];
    }
}

// ---------------------------------------------------------------------------
extern "C" void kernel_launch(void* const* d_in, const int* in_sizes, int n_in,
                              void* d_out, int out_size)
{
    const float* w_re   = (const float*)d_in[0];
    const float* w_im   = (const float*)d_in[1];
    const float* p_re   = (const float*)d_in[2];
    const float* p_im   = (const float*)d_in[3];
    const float* B_re   = (const float*)d_in[4];
    const float* B_im   = (const float*)d_in[5];
    const float* C_re   = (const float*)d_in[6];
    const float* C_im   = (const float*)d_in[7];
    const float* log_dt = (const float*)d_in[8];
    float* out = (float*)d_out;

    (void)in_sizes; (void)n_in; (void)out_size;

    cudaFuncSetAttribute(ifft_kernel,
                         cudaFuncAttributeMaxDynamicSharedMemorySize, 98304);

    dim3 grid1(8, HH);   // 8*128 threads * 4 l's = 4096 l's per h
    cauchy_kernel<<<grid1, 128>>>(w_re, w_im, p_re, p_im,
                                  B_re, B_im, C_re, C_im, log_dt);

    ifft_kernel<<<HH, 512, 98304>>>(out);
}

// round 5
// speedup vs baseline: 1.5162x; 1.1605x over previous
#include <cuda_runtime.h>
#include <math.h>

// Problem constants
#define HH      256
#define NPOLES  32
#define LLEN    8192
#define LH      4097
#define MHALF   4096
#define KSTRIDE 4104       // padded row stride (16B-aligned rows)

// Scratch: half-spectrum k_f per (h, l). 256*4104*8B = 8.4 MB.
__device__ float2 g_kf[HH * KSTRIDE];

typedef unsigned long long u64;

// ---- packed f32x2 helpers (sm_100a) ---------------------------------------
__device__ __forceinline__ u64 f2add(u64 a, u64 b) {
    u64 d; asm("add.rn.f32x2 %0,%1,%2;" : "=l"(d) : "l"(a), "l"(b)); return d;
}
__device__ __forceinline__ u64 f2mul(u64 a, u64 b) {
    u64 d; asm("mul.rn.f32x2 %0,%1,%2;" : "=l"(d) : "l"(a), "l"(b)); return d;
}
__device__ __forceinline__ u64 f2fma(u64 a, u64 b, u64 c) {
    u64 d; asm("fma.rn.f32x2 %0,%1,%2,%3;" : "=l"(d) : "l"(a), "l"(b), "l"(c)); return d;
}
__device__ __forceinline__ u64 f2rcp(u64 a) {
    u64 d;
    asm("{\n\t.reg .f32 lo,hi,rl,rh;\n\t"
        "mov.b64 {lo,hi}, %1;\n\t"
        "rcp.approx.f32 rl, lo;\n\t"
        "rcp.approx.f32 rh, hi;\n\t"
        "mov.b64 %0, {rl,rh};\n\t}" : "=l"(d) : "l"(a));
    return d;
}
__device__ __forceinline__ u64 pack2(float x, float y) {
    u64 d; asm("mov.b64 %0, {%1,%2};" : "=l"(d) : "f"(x), "f"(y)); return d;
}
__device__ __forceinline__ void unpack2(u64 a, float& x, float& y) {
    asm("mov.b64 {%0,%1}, %2;" : "=f"(x), "=f"(y) : "l"(a));
}

// per-lane Woodbury epilogue (im accumulators arrive negated)
__device__ __forceinline__ float2 woodbury(
    float r00r, float n00, float r01r, float n01,
    float r10r, float n10, float r11r, float n11, float t)
{
    const float r00i = -n00, r01i = -n01, r10i = -n10, r11i = -n11;
    const float dre  = 1.0f + r11r;
    const float dim  = r11i;
    const float dinv = __frcp_rn(fmaf(dre, dre, dim * dim));
    const float numre = r01r * r10r - r01i * r10i;
    const float numim = r01r * r10i + r01i * r10r;
    const float qre = (numre * dre + numim * dim) * dinv;
    const float qim = (numim * dre - numre * dim) * dinv;
    const float kwre = r00r - qre;
    const float kwim = r00i - qim;
    return make_float2(kwre - kwim * t, fmaf(kwre, t, kwim));
}

// ---------------------------------------------------------------------------
// Kernel 1: Cauchy + rank-1 Woodbury + bilinear scale -> g_kf[h][l]
//
// Stable per-pole-pair combination (z = i*zy, u = zy^2):
//   m1*m2 = (u - aw)^2 + 4*wr^2*u      (all-positive terms -> no cancellation)
//   re  += iv*[ C1*(u+aw) + C2*(u-aw) ]     C1=-2dt*wr*vr, C2=2dt*wi*vi
//   imn += zy*iv*[ K1*(u+cw) ] + zy*iv*K2   K1=2dt*vr,     K2=4dt*wr*wi*vi
// Const slots (u64): 0:AW 1:NAW 2:CW 3:FWR2; per e: 4+4e:C1 5:C2 6:K1 7:K2
// ---------------------------------------------------------------------------
__global__ __launch_bounds__(128) void cauchy_kernel(
    const float* __restrict__ w_re, const float* __restrict__ w_im,
    const float* __restrict__ p_re, const float* __restrict__ p_im,
    const float* __restrict__ B_re, const float* __restrict__ B_im,
    const float* __restrict__ C_re, const float* __restrict__ C_im,
    const float* __restrict__ log_dt)
{
    __shared__ float2 cst[NPOLES][20];

    const int h   = blockIdx.y;
    const int tid = threadIdx.x;

    if (tid < NPOLES) {
        const int n   = tid;
        const int idx = h * NPOLES + n;
        const float dt = expf(log_dt[h]);
        const float wr = w_re[idx] * dt;
        const float wi = w_im[idx] * dt;
        const float Br = B_re[idx], Bi = B_im[idx];
        const float Cr = C_re[idx], Ci = C_im[idx];
        const float Pr = p_re[idx], Pi = p_im[idx];
        const float aw = wr * wr + wi * wi;
        const float cw = wr * wr - wi * wi;
        const float d2 = 2.0f * dt;
        float2* cn = cst[n];
        cn[0] = make_float2(aw, aw);
        cn[1] = make_float2(-aw, -aw);
        cn[2] = make_float2(cw, cw);
        cn[3] = make_float2(4.0f * wr * wr, 4.0f * wr * wr);
        const float VR[4] = { Br * Cr - Bi * Ci,
                              Br * Pr + Bi * Pi,
                              Pr * Cr - Pi * Ci,
                              Pr * Pr + Pi * Pi };
        const float VI[4] = { Br * Ci + Bi * Cr,
                              Bi * Pr - Br * Pi,
                              Pr * Ci + Pi * Cr,
                              0.0f };
        #pragma unroll
        for (int e = 0; e < 4; e++) {
            float v;
            v = -d2 * wr * VR[e];            cn[4 + 4 * e] = make_float2(v, v); // C1
            v =  d2 * wi * VI[e];            cn[5 + 4 * e] = make_float2(v, v); // C2
            v =  d2 * VR[e];                 cn[6 + 4 * e] = make_float2(v, v); // K1
            v =  d2 * 2.0f * wr * wi * VI[e];cn[7 + 4 * e] = make_float2(v, v); // K2
        }
    }
    __syncthreads();

    // Nyquist bin (z -> inf): k_f = sum_n dt*Re(B*C) = sum 0.5*K1_00
    if (blockIdx.x == 0 && tid == 0) {
        float acc = 0.0f;
        #pragma unroll
        for (int n = 0; n < NPOLES; n++) acc += 0.5f * cst[n][6].x;
        g_kf[h * KSTRIDE + MHALF] = make_float2(acc, 0.0f);
    }

    const int l0 = (blockIdx.x * 128 + tid) * 4;

    float t0, t1, t2, t3;
    {
        float s, c;
        sincospif((float)(l0 + 0) * (1.0f / LLEN), &s, &c); t0 = __fdividef(s, c);
        sincospif((float)(l0 + 1) * (1.0f / LLEN), &s, &c); t1 = __fdividef(s, c);
        sincospif((float)(l0 + 2) * (1.0f / LLEN), &s, &c); t2 = __fdividef(s, c);
        sincospif((float)(l0 + 3) * (1.0f / LLEN), &s, &c); t3 = __fdividef(s, c);
    }
    u64 zz[2], uu[2];
    zz[0] = pack2(2.0f * t0, 2.0f * t1);
    zz[1] = pack2(2.0f * t2, 2.0f * t3);
    uu[0] = f2mul(zz[0], zz[0]);
    uu[1] = f2mul(zz[1], zz[1]);

    u64 accR[2][4], accN[2][4];
    #pragma unroll
    for (int pr = 0; pr < 2; pr++)
        #pragma unroll
        for (int e = 0; e < 4; e++) { accR[pr][e] = 0; accN[pr][e] = 0; }

    #pragma unroll 4
    for (int n = 0; n < NPOLES; n++) {
        const u64* cn = reinterpret_cast<const u64*>(cst[n]);
        const u64 AW   = cn[0];
        const u64 NAW  = cn[1];
        const u64 CW   = cn[2];
        const u64 FWR2 = cn[3];
        #pragma unroll
        for (int pr = 0; pr < 2; pr++) {
            const u64 u  = uu[pr];
            const u64 c1 = f2add(u, AW);            // u + aw
            const u64 c2 = f2add(u, NAW);           // u - aw
            const u64 c3 = f2add(u, CW);            // u + cw
            const u64 m  = f2fma(c2, c2, f2mul(u, FWR2));
            const u64 iv = f2rcp(m);
            const u64 ti = f2mul(zz[pr], iv);
            const u64 p1 = f2mul(c1, iv);
            const u64 p2 = f2mul(c2, iv);
            const u64 gi = f2mul(c3, ti);
            #pragma unroll
            for (int e = 0; e < 3; e++) {
                accR[pr][e] = f2fma(cn[4 + 4 * e], p1, f2fma(cn[5 + 4 * e], p2, accR[pr][e]));
                accN[pr][e] = f2fma(cn[6 + 4 * e], gi, f2fma(cn[7 + 4 * e], ti, accN[pr][e]));
            }
            accR[pr][3] = f2fma(cn[16], p1, accR[pr][3]);   // v11: vi = 0
            accN[pr][3] = f2fma(cn[18], gi, accN[pr][3]);
        }
    }

    // epilogue
    float rr[4][4], nn[4][4];   // [lane l][entry]
    #pragma unroll
    for (int pr = 0; pr < 2; pr++)
        #pragma unroll
        for (int e = 0; e < 4; e++) {
            unpack2(accR[pr][e], rr[2 * pr][e], rr[2 * pr + 1][e]);
            unpack2(accN[pr][e], nn[2 * pr][e], nn[2 * pr + 1][e]);
        }

    const float tt[4] = { t0, t1, t2, t3 };
    float2 kf[4];
    #pragma unroll
    for (int i = 0; i < 4; i++)
        kf[i] = woodbury(rr[i][0], nn[i][0], rr[i][1], nn[i][1],
                         rr[i][2], nn[i][2], rr[i][3], nn[i][3], tt[i]);

    float2* row = g_kf + h * KSTRIDE;
    reinterpret_cast<float4*>(row + l0)[0]     = make_float4(kf[0].x, kf[0].y, kf[1].x, kf[1].y);
    reinterpret_cast<float4*>(row + l0 + 2)[0] = make_float4(kf[2].x, kf[2].y, kf[3].x, kf[3].y);
}

// ---------------------------------------------------------------------------
// Kernel 2: per-h irfft(8192) via M=4096 radix-8 Stockham inverse FFT.
// 4 stages (s = 1, 8, 64, 512), padded buffers, [k][p] twiddle tables.
// ---------------------------------------------------------------------------
#define PADIDX(i) ((i) + ((i) >> 3))

__device__ __forceinline__ u64 csub(u64 a, u64 b) {
    const u64 NEG1 = 0xBF800000BF800000ULL;   // (-1.f, -1.f)
    return f2fma(b, NEG1, a);
}
__device__ __forceinline__ u64 cmuli(u64 a) {     // * i : (x,y) -> (-y,x)
    float x, y; unpack2(a, x, y);
    return pack2(-y, x);
}
__device__ __forceinline__ u64 cmul(u64 a, u64 w) {
    float ax, ay, wx, wy; unpack2(a, ax, ay); unpack2(w, wx, wy);
    return pack2(fmaf(ax, wx, -ay * wy), fmaf(ax, wy, ay * wx));
}

template<int S, int LS, int M, bool TW>
__device__ __forceinline__ void fft_stage(const float2* __restrict__ src,
                                          float2* __restrict__ dst,
                                          const float2* __restrict__ twt,
                                          int tid)
{
    const int q = tid & (S - 1);
    const int p = tid >> LS;
    const int base = q + S * p;

    u64 x[8];
    #pragma unroll
    for (int j = 0; j < 8; j++)
        x[j] = *reinterpret_cast<const u64*>(&src[PADIDX(base + j * 512)]);

    // even DFT4 on (x0,x2,x4,x6); odd DFT4 on (x1,x3,x5,x7); sign +i (inverse)
    u64 ta = f2add(x[0], x[4]), tb = csub(x[0], x[4]);
    u64 tc = f2add(x[2], x[6]), td = csub(x[2], x[6]);
    u64 E0 = f2add(ta, tc), E2 = csub(ta, tc);
    u64 itd = cmuli(td);
    u64 E1 = f2add(tb, itd), E3 = csub(tb, itd);

    u64 oa = f2add(x[1], x[5]), ob = csub(x[1], x[5]);
    u64 oc = f2add(x[3], x[7]), od = csub(x[3], x[7]);
    u64 O0 = f2add(oa, oc), O2 = csub(oa, oc);
    u64 iod = cmuli(od);
    u64 O1 = f2add(ob, iod), O3 = csub(ob, iod);

    const float SQ = 0.70710678118654752f;
    float o1x, o1y, o3x, o3y;
    unpack2(O1, o1x, o1y); unpack2(O3, o3x, o3y);
    const u64 W1 = pack2(SQ * (o1x - o1y), SQ * (o1x + o1y));   // w^1 * O1
    const u64 W2 = cmuli(O2);                                    // w^2 * O2
    const u64 W3 = pack2(-SQ * (o3x + o3y), SQ * (o3x - o3y));   // w^3 * O3

    u64 y[8];
    y[0] = f2add(E0, O0); y[4] = csub(E0, O0);
    y[1] = f2add(E1, W1); y[5] = csub(E1, W1);
    y[2] = f2add(E2, W2); y[6] = csub(E2, W2);
    y[3] = f2add(E3, W3); y[7] = csub(E3, W3);

    const int obase = q + S * 8 * p;
    *reinterpret_cast<u64*>(&dst[PADIDX(obase)]) = y[0];
    #pragma unroll
    for (int k = 1; k < 8; k++) {
        u64 v = y[k];
        if (TW) {
            const u64 w = *reinterpret_cast<const u64*>(&twt[(k - 1) * M + p]);
            v = cmul(v, w);
        }
        *reinterpret_cast<u64*>(&dst[PADIDX(obase + S * k)]) = v;
    }
}

// smem (float2 units): bufA[4608] bufB[4608] tw1[3584] tw8[448] tw64[56]
#define SM_TOTAL_F2 (4608 + 4608 + 3584 + 448 + 56)

__global__ __launch_bounds__(512) void ifft_kernel(float* __restrict__ out)
{
    extern __shared__ float2 sh[];
    float2* bufA = sh;
    float2* bufB = sh + 4608;
    float2* tw1  = sh + 9216;
    float2* tw8  = sh + 12800;
    float2* tw64 = sh + 13248;

    const int h   = blockIdx.x;
    const int tid = threadIdx.x;

    // build stage twiddle tables: [k-1][p] = e^{+2pi i p k / Nt}
    for (int i = tid; i < 3584; i += 512) {
        const int k = (i >> 9) + 1, p = i & 511;
        float s, c; sincospif((float)(p * k) * (1.0f / 2048.0f), &s, &c);
        tw1[i] = make_float2(c, s);
    }
    if (tid < 448) {
        const int k = (tid >> 6) + 1, p = tid & 63;
        float s, c; sincospif((float)(p * k) * (1.0f / 256.0f), &s, &c);
        tw8[tid] = make_float2(c, s);
    }
    if (tid < 56) {
        const int k = (tid >> 3) + 1, p = tid & 7;
        float s, c; sincospif((float)(p * k) * (1.0f / 32.0f), &s, &c);
        tw64[tid] = make_float2(c, s);
    }

    // C2R unpack into bufA (padded), scale folded
    const float scale = 1.0f / (float)MHALF;
    const float2* __restrict__ K = &g_kf[h * KSTRIDE];
    for (int k = tid; k < MHALF; k += 512) {
        float2 Kk = K[k];
        float2 Km = K[MHALF - k];
        if (k == 0) { Kk.y = 0.0f; Km.y = 0.0f; }
        const float Ere = 0.5f * (Kk.x + Km.x);
        const float Eim = 0.5f * (Kk.y - Km.y);
        const float Dre = 0.5f * (Kk.x - Km.x);
        const float Dim = 0.5f * (Kk.y + Km.y);
        float tws, twc;
        sincospif((float)k * (1.0f / MHALF), &tws, &twc);   // e^{+2pi i k/8192}
        const float Ore = Dre * twc - Dim * tws;
        const float Oim = Dre * tws + Dim * twc;
        bufA[PADIDX(k)] = make_float2((Ere - Oim) * scale, (Eim + Ore) * scale);
    }
    __syncthreads();

    fft_stage<1,   0, 512, true >(bufA, bufB, tw1,  tid); __syncthreads();
    fft_stage<8,   3, 64,  true >(bufB, bufA, tw8,  tid); __syncthreads();
    fft_stage<64,  6, 8,   true >(bufA, bufB, tw64, tid); __syncthreads();
    fft_stage<512, 9, 1,   false>(bufB, bufA, (const float2*)0, tid); __syncthreads();

    float2* o2 = reinterpret_cast<float2*>(out) + (size_t)h * MHALF;
    for (int m2 = tid; m2 < MHALF; m2 += 512) {
        o2[m2] = bufA[PADIDX(m2)];
    }
}

// ---------------------------------------------------------------------------
extern "C" void kernel_launch(void* const* d_in, const int* in_sizes, int n_in,
                              void* d_out, int out_size)
{
    const float* w_re   = (const float*)d_in[0];
    const float* w_im   = (const float*)d_in[1];
    const float* p_re   = (const float*)d_in[2];
    const float* p_im   = (const float*)d_in[3];
    const float* B_re   = (const float*)d_in[4];
    const float* B_im   = (const float*)d_in[5];
    const float* C_re   = (const float*)d_in[6];
    const float* C_im   = (const float*)d_in[7];
    const float* log_dt = (const float*)d_in[8];
    float* out = (float*)d_out;

    (void)in_sizes; (void)n_in; (void)out_size;

    cudaFuncSetAttribute(ifft_kernel,
                         cudaFuncAttributeMaxDynamicSharedMemorySize,
                         SM_TOTAL_F2 * (int)sizeof(float2));

    dim3 grid1(8, HH);   // 8*128 threads * 4 l's = 4096 l's per h
    cauchy_kernel<<<grid1, 128>>>(w_re, w_im, p_re, p_im,
                                  B_re, B_im, C_re, C_im, log_dt);

    ifft_kernel<<<HH, 512, SM_TOTAL_F2 * (int)sizeof(float2)>>>(out);
}